// round 3
// baseline (speedup 1.0000x reference)
#include <cuda_runtime.h>
#include <cstdint>

#define NN 4096
#define CAP 512          // max neighbors per row (mean ~82, 48 sigma headroom)
#define NG 64
#define OUTC 10

// ---------------- scratch (device globals; no allocation allowed) ------------
__device__ int   g_deg[NN];
__device__ int   g_nbr[NN * CAP];          // 8 MB
__device__ float g_f[NN * 64];             // per-layer features [N][k*32+h]
__device__ float g_s1[2 * NN];
__device__ float g_s2[2 * NN];
__device__ float g_h[NN * 192];            // concat of relu'd layer outputs

// ---------------- 1) build sparse adjacency (CSR-ish, deterministic) ---------
__global__ void build_adj_kernel(const float* __restrict__ adj) {
    int row = blockIdx.x;
    int t   = threadIdx.x;               // 256 threads
    const float* arow = adj + (size_t)row * NN;

    // coalesced strided scan: thread t owns columns t, t+256, ... (16 each)
    int loc[16];
    int cnt = 0;
#pragma unroll
    for (int u = 0; u < 16; ++u) {
        int j = t + u * 256;
        if (arow[j] > 0.f) loc[cnt++] = j;
    }
    __shared__ int sc[256];
    __shared__ int soff[257];
    sc[t] = cnt;
    __syncthreads();
    if (t == 0) {
        int s = 0;
        for (int i = 0; i < 256; ++i) { soff[i] = s; s += sc[i]; }
        soff[256] = s;
        g_deg[row] = s;
    }
    __syncthreads();
    int off = row * CAP + soff[t];
    for (int u = 0; u < cnt; ++u) g_nbr[off + u] = loc[u];
}

// ---------------- 2) feature GEMM: f = in @ W + b  (both heads fused) --------
// in: layer0 -> external x (stride 512); layer1/2 -> g_h + (l-1)*64 (stride 192)
// W layout: [K=2][in_dim][32];  f out: [N][64] with t = k*32+h
__global__ void gemm_f_kernel(const float* __restrict__ x_ext,
                              const float* __restrict__ W,
                              const float* __restrict__ b,
                              int in_dim, int layer) {
    const float* in;
    int stride;
    if (layer == 0) { in = x_ext; stride = 512; }
    else            { in = g_h + (layer - 1) * 64; stride = 192; }

    int row0 = blockIdx.x * 16;
    int tid  = threadIdx.x;              // 256
    int t    = tid & 63;                 // output column (k*32+h)
    int rg   = tid >> 6;                 // 0..3

    __shared__ float xs[16][64];
    __shared__ float ws[64][64];

    float acc0 = 0.f, acc1 = 0.f, acc2 = 0.f, acc3 = 0.f;

    for (int t0 = 0; t0 < in_dim; t0 += 64) {
#pragma unroll
        for (int idx = tid; idx < 16 * 64; idx += 256) {
            int r = idx >> 6, d = idx & 63;
            xs[r][d] = in[(size_t)(row0 + r) * stride + t0 + d];
        }
#pragma unroll
        for (int idx = tid; idx < 64 * 64; idx += 256) {
            int d = idx >> 6, tt = idx & 63;
            int kk = tt >> 5, hh = tt & 31;
            ws[d][tt] = W[(size_t)kk * in_dim * 32 + (size_t)(t0 + d) * 32 + hh];
        }
        __syncthreads();
#pragma unroll
        for (int dd = 0; dd < 64; ++dd) {
            float wv = ws[dd][t];
            acc0 += xs[rg     ][dd] * wv;
            acc1 += xs[rg +  4][dd] * wv;
            acc2 += xs[rg +  8][dd] * wv;
            acc3 += xs[rg + 12][dd] * wv;
        }
        __syncthreads();
    }
    float bb = b[t];
    g_f[(size_t)(row0 + rg     ) * 64 + t] = acc0 + bb;
    g_f[(size_t)(row0 + rg +  4) * 64 + t] = acc1 + bb;
    g_f[(size_t)(row0 + rg +  8) * 64 + t] = acc2 + bb;
    g_f[(size_t)(row0 + rg + 12) * 64 + t] = acc3 + bb;
}

// ---------------- 3) attention score vectors s1, s2 --------------------------
__global__ void compute_s_kernel(const float* __restrict__ a1w,
                                 const float* __restrict__ a1b,
                                 const float* __restrict__ a2w,
                                 const float* __restrict__ a2b) {
    int i = blockIdx.x;
    int t = threadIdx.x;                 // 64 (warp 0 = head 0, warp 1 = head 1)
    int k = t >> 5, h = t & 31;
    float fv = g_f[(size_t)i * 64 + t];
    float v1 = fv * a1w[k * 32 + h];
    float v2 = fv * a2w[k * 32 + h];
#pragma unroll
    for (int o = 16; o > 0; o >>= 1) {
        v1 += __shfl_down_sync(0xffffffffu, v1, o);
        v2 += __shfl_down_sync(0xffffffffu, v2, o);
    }
    if (h == 0) {
        g_s1[k * NN + i] = v1 + a1b[k];
        g_s2[k * NN + i] = v2 + a2b[k];
    }
}

// ---------------- 4) sparse softmax-attention aggregate + relu ---------------
// block = one row, warp k = head k, lane = feature dim h
__global__ void attn_kernel(int layer) {
    int i    = blockIdx.x;
    int t    = threadIdx.x;
    int k    = t >> 5;
    int lane = t & 31;
    int deg  = g_deg[i];
    int base = i * CAP;

    float s1i = g_s1[k * NN + i];
    const float* s2p = g_s2 + k * NN;

    // pass 1: row max of leaky_relu(e)
    float m = -1e30f;
    for (int idx = lane; idx < deg; idx += 32) {
        int j = g_nbr[base + idx];
        float e = s1i + s2p[j];
        e = (e >= 0.f) ? e : 0.01f * e;
        m = fmaxf(m, e);
    }
#pragma unroll
    for (int o = 16; o > 0; o >>= 1) m = fmaxf(m, __shfl_xor_sync(0xffffffffu, m, o));

    // pass 2: exp weights + weighted aggregate of f rows
    float acc = 0.f, dsum = 0.f;
    int nch = (deg + 31) >> 5;
    for (int c = 0; c < nch; ++c) {
        int idx = c * 32 + lane;
        int j = 0;
        float w = 0.f;
        if (idx < deg) {
            j = g_nbr[base + idx];
            float e = s1i + s2p[j];
            e = (e >= 0.f) ? e : 0.01f * e;
            w = __expf(e - m);
        }
        dsum += w;
        int lim = min(32, deg - c * 32);
        for (int l = 0; l < lim; ++l) {
            float wl = __shfl_sync(0xffffffffu, w, l);
            int   jl = __shfl_sync(0xffffffffu, j, l);
            acc += wl * g_f[(size_t)jl * 64 + k * 32 + lane];  // coalesced 128B
        }
    }
#pragma unroll
    for (int o = 16; o > 0; o >>= 1) dsum += __shfl_xor_sync(0xffffffffu, dsum, o);

    float out = acc / dsum;
    out = (out > 0.f) ? out : 0.f;       // relu (fused; concat layout)
    g_h[(size_t)i * 192 + layer * 64 + t] = out;
}

// ---------------- 5) segment-mean pool + final linear + softmax --------------
__global__ void pool_kernel(const int* __restrict__ batch,
                            const float* __restrict__ Wf,
                            const float* __restrict__ bf,
                            float* __restrict__ out) {
    int g = blockIdx.x;                  // 64 graphs
    int c = threadIdx.x;                 // 192 threads

    // batch is sorted: binary-search segment bounds
    int lo = 0, hi = NN;
    while (lo < hi) { int mid = (lo + hi) >> 1; if (batch[mid] < g) lo = mid + 1; else hi = mid; }
    int start = lo;
    lo = start; hi = NN;
    while (lo < hi) { int mid = (lo + hi) >> 1; if (batch[mid] < g + 1) lo = mid + 1; else hi = mid; }
    int end = lo;
    int cnt = end - start;

    float accv = 0.f;
    for (int i = start; i < end; ++i) accv += g_h[(size_t)i * 192 + c];

    __shared__ float sp[192];
    __shared__ float lg[OUTC];
    sp[c] = accv / fmaxf((float)cnt, 1.f);
    __syncthreads();

    if (c < OUTC) {
        float a = bf[c];
        for (int d = 0; d < 192; ++d) a += sp[d] * Wf[d * OUTC + c];
        lg[c] = a;
    }
    __syncthreads();
    if (c < OUTC) {
        float mx = -1e30f;
#pragma unroll
        for (int o = 0; o < OUTC; ++o) mx = fmaxf(mx, lg[o]);
        float s = 0.f;
#pragma unroll
        for (int o = 0; o < OUTC; ++o) s += __expf(lg[o] - mx);
        out[g * OUTC + c] = __expf(lg[c] - mx) / s;
    }
}

// ---------------- launch -----------------------------------------------------
extern "C" void kernel_launch(void* const* d_in, const int* in_sizes, int n_in,
                              void* d_out, int out_size) {
    const float* x     = (const float*)d_in[0];
    const float* adj   = (const float*)d_in[1];
    const int*   batch = (const int*)  d_in[2];
    // params in order: (W,b,a1w,a1b,a2w,a2b) x3 layers, then Wf, bf
    const float* P[20];
    for (int i = 0; i < 20; ++i) P[i] = (const float*)d_in[3 + i];

    build_adj_kernel<<<NN, 256>>>(adj);

    for (int l = 0; l < 3; ++l) {
        const float* W   = P[l * 6 + 0];
        const float* b   = P[l * 6 + 1];
        const float* a1w = P[l * 6 + 2];
        const float* a1b = P[l * 6 + 3];
        const float* a2w = P[l * 6 + 4];
        const float* a2b = P[l * 6 + 5];
        int in_dim = (l == 0) ? 512 : 64;
        gemm_f_kernel<<<NN / 16, 256>>>(x, W, b, in_dim, l);
        compute_s_kernel<<<NN, 64>>>(a1w, a1b, a2w, a2b);
        attn_kernel<<<NN, 64>>>(l);
    }

    pool_kernel<<<NG, 192>>>(batch, P[18], P[19], (float*)d_out);
}

// round 4
// speedup vs baseline: 1.1269x; 1.1269x over previous
#include <cuda_runtime.h>
#include <cstdint>

#define NN 4096
#define CAP 512          // max neighbors per row (mean ~83, huge headroom)
#define NG 64
#define OUTC 10

// ---------------- scratch (device globals; no allocation allowed) ------------
__device__ int   g_deg[NN];
__device__ int   g_nbr[NN * CAP];                    // 8 MB, ascending per row
__device__ float g_f[NN * 64];                       // [N][k*32+h]
__device__ __align__(8) float g_s1v[2 * NN];         // [i*2 + k]
__device__ __align__(8) float g_s2v[2 * NN];         // [i*2 + k]
__device__ float g_h[NN * 192];                      // concat of relu'd outputs

// ---------------- 1) build sparse adjacency (sorted, deterministic) ----------
// thread t owns contiguous columns [16t, 16t+16) -> list globally ascending
__global__ void build_adj_kernel(const float* __restrict__ adj) {
    int row  = blockIdx.x;
    int t    = threadIdx.x;              // 256
    int lane = t & 31, warp = t >> 5;
    const float4* arow = (const float4*)(adj + (size_t)row * NN);

    int loc[16];
    int cnt = 0;
    int c0 = t * 16;
#pragma unroll
    for (int v = 0; v < 4; ++v) {
        float4 q = arow[t * 4 + v];
        if (q.x > 0.f) loc[cnt++] = c0 + v * 4 + 0;
        if (q.y > 0.f) loc[cnt++] = c0 + v * 4 + 1;
        if (q.z > 0.f) loc[cnt++] = c0 + v * 4 + 2;
        if (q.w > 0.f) loc[cnt++] = c0 + v * 4 + 3;
    }
    // exclusive prefix of cnt across 256 threads: warp scan + warp-sum scan
    int x = cnt;
#pragma unroll
    for (int o = 1; o < 32; o <<= 1) {
        int y = __shfl_up_sync(0xffffffffu, x, o);
        if (lane >= o) x += y;
    }
    __shared__ int wsum[8];
    if (lane == 31) wsum[warp] = x;
    __syncthreads();
    if (t == 0) {
        int s = 0;
#pragma unroll
        for (int w = 0; w < 8; ++w) { int y = wsum[w]; wsum[w] = s; s += y; }
        g_deg[row] = s;
    }
    __syncthreads();
    int off = row * CAP + wsum[warp] + (x - cnt);
    for (int u = 0; u < cnt; ++u) g_nbr[off + u] = loc[u];
}

// ---------------- 2) fused feature GEMM + attention score vectors ------------
// f = in @ W + b; s1 = f@a1w + a1b; s2 = f@a2w + a2b (both heads).
// 256 threads, 16 rows/block. warp = (rg, head): t = tid&63, rg = tid>>6.
__global__ __launch_bounds__(256) void gemm_f_kernel(
        const float* __restrict__ x_ext,
        const float* __restrict__ W,  const float* __restrict__ b,
        const float* __restrict__ a1w, const float* __restrict__ a1b,
        const float* __restrict__ a2w, const float* __restrict__ a2b,
        int in_dim, int layer) {
    const float* in;
    int stride;
    if (layer == 0) { in = x_ext; stride = 512; }
    else            { in = g_h + (layer - 1) * 64; stride = 192; }

    int row0 = blockIdx.x * 16;
    int tid  = threadIdx.x;
    int t    = tid & 63;                 // output col (k*32+h)
    int rg   = tid >> 6;                 // 0..3 -> rows rg*4 .. rg*4+3
    int lane = tid & 31;
    int k    = (tid >> 5) & 1;           // head (warp-aligned)

    __shared__ float xs[64][20];         // [d][r], padded (80B rows, 16B-aligned)
    __shared__ float ws[64][64];

    float acc0 = 0.f, acc1 = 0.f, acc2 = 0.f, acc3 = 0.f;

    for (int t0 = 0; t0 < in_dim; t0 += 64) {
        for (int idx = tid; idx < 16 * 64; idx += 256) {
            int r = idx >> 6, d = idx & 63;
            xs[d][r] = in[(size_t)(row0 + r) * stride + t0 + d];
        }
        for (int idx = tid; idx < 64 * 64; idx += 256) {
            int d = idx >> 6, tt = idx & 63;
            int kk = tt >> 5, hh = tt & 31;
            ws[d][tt] = W[(size_t)kk * in_dim * 32 + (size_t)(t0 + d) * 32 + hh];
        }
        __syncthreads();
#pragma unroll
        for (int dd = 0; dd < 64; ++dd) {
            float4 xv = *(const float4*)&xs[dd][rg * 4];
            float  wv = ws[dd][t];
            acc0 += xv.x * wv;
            acc1 += xv.y * wv;
            acc2 += xv.z * wv;
            acc3 += xv.w * wv;
        }
        __syncthreads();
    }
    float bb = b[t];
    acc0 += bb; acc1 += bb; acc2 += bb; acc3 += bb;
    int r0 = row0 + rg * 4;
    g_f[(size_t)(r0 + 0) * 64 + t] = acc0;
    g_f[(size_t)(r0 + 1) * 64 + t] = acc1;
    g_f[(size_t)(r0 + 2) * 64 + t] = acc2;
    g_f[(size_t)(r0 + 3) * 64 + t] = acc3;

    // ---- fused s1/s2: per warp (head k), reduce over 32 lanes, 4 rows ----
    float w1 = a1w[t], w2 = a2w[t];
    float b1v = a1b[k], b2v = a2b[k];
    float av[4] = {acc0, acc1, acc2, acc3};
#pragma unroll
    for (int q = 0; q < 4; ++q) {
        float v1 = av[q] * w1;
        float v2 = av[q] * w2;
#pragma unroll
        for (int o = 16; o > 0; o >>= 1) {
            v1 += __shfl_down_sync(0xffffffffu, v1, o);
            v2 += __shfl_down_sync(0xffffffffu, v2, o);
        }
        if (lane == 0) {
            g_s1v[(r0 + q) * 2 + k] = v1 + b1v;
            g_s2v[(r0 + q) * 2 + k] = v2 + b2v;
        }
    }
}

// ---------------- 3) sparse softmax-attention aggregate + relu ---------------
// block = one row, 128 threads. Phase A: all threads score both heads (one
// float2 gather per edge), cache e & j in smem. Phase B: warps (2k, 2k+1)
// split head k's chunks; 4 accumulators; combine via smem.
__global__ __launch_bounds__(128) void attn_kernel(int layer) {
    int i    = blockIdx.x;
    int tid  = threadIdx.x;
    int warp = tid >> 5;
    int lane = tid & 31;
    int deg  = g_deg[i];
    int base = i * CAP;

    __shared__ float se[2][CAP];
    __shared__ int   sj[CAP];
    __shared__ float smax[2][4];
    __shared__ float sacc[4][32];
    __shared__ float sds[4];

    float2 s1 = *(const float2*)&g_s1v[i * 2];

    // Phase A: score both heads per edge, single scattered float2 gather
    float m0 = -1e30f, m1 = -1e30f;
    for (int idx = tid; idx < deg; idx += 128) {
        int j = g_nbr[base + idx];
        sj[idx] = j;
        float2 s2 = *(const float2*)&g_s2v[j * 2];
        float e0 = s1.x + s2.x; e0 = (e0 >= 0.f) ? e0 : 0.01f * e0;
        float e1 = s1.y + s2.y; e1 = (e1 >= 0.f) ? e1 : 0.01f * e1;
        se[0][idx] = e0;
        se[1][idx] = e1;
        m0 = fmaxf(m0, e0);
        m1 = fmaxf(m1, e1);
    }
#pragma unroll
    for (int o = 16; o > 0; o >>= 1) {
        m0 = fmaxf(m0, __shfl_xor_sync(0xffffffffu, m0, o));
        m1 = fmaxf(m1, __shfl_xor_sync(0xffffffffu, m1, o));
    }
    if (lane == 0) { smax[0][warp] = m0; smax[1][warp] = m1; }
    __syncthreads();

    int k    = warp >> 1;    // head for phase B
    int half = warp & 1;     // chunk parity
    float m = fmaxf(fmaxf(smax[k][0], smax[k][1]),
                    fmaxf(smax[k][2], smax[k][3]));

    // Phase B
    float a0 = 0.f, a1 = 0.f, a2 = 0.f, a3 = 0.f, dsum = 0.f;
    const float* fcol = g_f + k * 32 + lane;
    int nch = (deg + 31) >> 5;
    for (int c = half; c < nch; c += 2) {
        int idx = c * 32 + lane;
        int j = 0;
        float w = 0.f;
        if (idx < deg) {
            j = sj[idx];
            w = __expf(se[k][idx] - m);
        }
        dsum += w;
        int lim = min(32, deg - c * 32);
        int l = 0;
        for (; l + 4 <= lim; l += 4) {
            float w0 = __shfl_sync(0xffffffffu, w, l + 0);
            int   j0 = __shfl_sync(0xffffffffu, j, l + 0);
            float w1 = __shfl_sync(0xffffffffu, w, l + 1);
            int   j1 = __shfl_sync(0xffffffffu, j, l + 1);
            float w2 = __shfl_sync(0xffffffffu, w, l + 2);
            int   j2 = __shfl_sync(0xffffffffu, j, l + 2);
            float w3 = __shfl_sync(0xffffffffu, w, l + 3);
            int   j3 = __shfl_sync(0xffffffffu, j, l + 3);
            a0 += w0 * fcol[(size_t)j0 * 64];
            a1 += w1 * fcol[(size_t)j1 * 64];
            a2 += w2 * fcol[(size_t)j2 * 64];
            a3 += w3 * fcol[(size_t)j3 * 64];
        }
        for (; l < lim; ++l) {
            float wl = __shfl_sync(0xffffffffu, w, l);
            int   jl = __shfl_sync(0xffffffffu, j, l);
            a0 += wl * fcol[(size_t)jl * 64];
        }
    }
    float acc = (a0 + a1) + (a2 + a3);
#pragma unroll
    for (int o = 16; o > 0; o >>= 1) dsum += __shfl_xor_sync(0xffffffffu, dsum, o);

    sacc[warp][lane] = acc;
    if (lane == 0) sds[warp] = dsum;
    __syncthreads();

    if (warp < 2) {  // warp kk writes head kk
        int kk = warp;
        float tot = sacc[2 * kk][lane] + sacc[2 * kk + 1][lane];
        float d   = sds[2 * kk] + sds[2 * kk + 1];
        float out = tot / d;
        out = (out > 0.f) ? out : 0.f;   // relu fused, concat layout
        g_h[(size_t)i * 192 + layer * 64 + kk * 32 + lane] = out;
    }
}

// ---------------- 4) segment-mean pool + final linear + softmax --------------
__global__ void pool_kernel(const int* __restrict__ batch,
                            const float* __restrict__ Wf,
                            const float* __restrict__ bf,
                            float* __restrict__ out) {
    int g = blockIdx.x;                  // 64 graphs
    int c = threadIdx.x;                 // 192 threads

    int lo = 0, hi = NN;
    while (lo < hi) { int mid = (lo + hi) >> 1; if (batch[mid] < g) lo = mid + 1; else hi = mid; }
    int start = lo;
    lo = start; hi = NN;
    while (lo < hi) { int mid = (lo + hi) >> 1; if (batch[mid] < g + 1) lo = mid + 1; else hi = mid; }
    int end = lo;
    int cnt = end - start;

    float accv = 0.f;
    for (int i = start; i < end; ++i) accv += g_h[(size_t)i * 192 + c];

    __shared__ float sp[192];
    __shared__ float lg[OUTC];
    sp[c] = accv / fmaxf((float)cnt, 1.f);
    __syncthreads();

    if (c < OUTC) {
        float a = bf[c];
        for (int d = 0; d < 192; ++d) a += sp[d] * Wf[d * OUTC + c];
        lg[c] = a;
    }
    __syncthreads();
    if (c < OUTC) {
        float mx = -1e30f;
#pragma unroll
        for (int o = 0; o < OUTC; ++o) mx = fmaxf(mx, lg[o]);
        float s = 0.f;
#pragma unroll
        for (int o = 0; o < OUTC; ++o) s += __expf(lg[o] - mx);
        out[g * OUTC + c] = __expf(lg[c] - mx) / s;
    }
}

// ---------------- launch -----------------------------------------------------
extern "C" void kernel_launch(void* const* d_in, const int* in_sizes, int n_in,
                              void* d_out, int out_size) {
    const float* x     = (const float*)d_in[0];
    const float* adj   = (const float*)d_in[1];
    const int*   batch = (const int*)  d_in[2];
    const float* P[20];
    for (int i = 0; i < 20; ++i) P[i] = (const float*)d_in[3 + i];

    build_adj_kernel<<<NN, 256>>>(adj);

    for (int l = 0; l < 3; ++l) {
        int in_dim = (l == 0) ? 512 : 64;
        gemm_f_kernel<<<NN / 16, 256>>>(x, P[l * 6 + 0], P[l * 6 + 1],
                                        P[l * 6 + 2], P[l * 6 + 3],
                                        P[l * 6 + 4], P[l * 6 + 5],
                                        in_dim, l);
        attn_kernel<<<NN, 128>>>(l);
    }

    pool_kernel<<<NG, 192>>>(batch, P[18], P[19], (float*)d_out);
}